// round 1
// baseline (speedup 1.0000x reference)
#include <cuda_runtime.h>
#include <math.h>
#include <stdint.h>

// Problem constants
#define Bq   8
#define Cc   128
#define Hh   128
#define Wd   128
#define Nn   16384          // H*W
#define NHh  8
#define HDd  16
#define Mtot (Bq * Nn)      // 131072

#define PI_F 3.14159265358979f

// ---------------- scratch (static device arrays; no allocations) -------------
__device__ float g_xf[(size_t)Mtot * Cc];        // [B,N,C] post-LN          64 MB
__device__ float g_qkv[(size_t)Mtot * 3 * Cc];   // [B,N,3C]                192 MB
__device__ float g_attn[(size_t)Mtot * Cc];      // [B,N,C] attention out    64 MB
__device__ float g_tmp[(size_t)Mtot * Cc];       // [B,N,C] post-proj        64 MB
__device__ float g_ctx[64 * 272];                // per (b,head): 256 ctx + 16 ksum

// =============================================================================
// Kernel A: polar features + depthwise 3x3 conv + channel LayerNorm
// block = (b,h) row; 256 threads; writes xf in [B,N,C]
// dyn smem: e_sm[128][129] + pf[2][3][128] + stats[256]
// =============================================================================
#define SMEM_A ((128 * 129 + 2 * 3 * 128 + 256) * 4)

__global__ void conv_ln_kernel(const float* __restrict__ x,
                               const float* __restrict__ conv_w,
                               const float* __restrict__ conv_b,
                               const float* __restrict__ ln_g,
                               const float* __restrict__ ln_b)
{
    extern __shared__ float sm[];
    float* e_sm = sm;                       // [128][129]
    float* pf_sm = sm + 128 * 129;          // [2][3][128]
    float* stat = pf_sm + 2 * 3 * 128;      // mu[128], rinv[128]

    const int h = blockIdx.x;
    const int b = blockIdx.y;
    const int tid = threadIdx.x;            // 256

    // precompute rho/theta for rows h-1..h+1
    for (int i = tid; i < 3 * 128; i += 256) {
        int r = i >> 7, w = i & 127;
        float yc = (float)(h + r - 1 - 64);
        float xc = (float)(w - 64);
        float rho = sqrtf(xc * xc + yc * yc) * (1.0f / 64.0f);
        float th  = (atan2f(yc, xc) + PI_F) * (1.0f / (2.0f * PI_F));
        pf_sm[0 * 384 + i] = rho;   // even channels
        pf_sm[1 * 384 + i] = th;    // odd channels
    }
    __syncthreads();

    // stage 1: depthwise conv for all 128 channels of this (b,h) row
    const int w = tid & 127;
    const int sub = tid >> 7;               // 0 or 1: two channels at a time
    for (int c = sub; c < 128; c += 2) {
        const float* xp = x + ((size_t)b * 128 + c) * (size_t)Nn;
        const float* wp = conv_w + c * 9;
        float wg[9];
        #pragma unroll
        for (int i = 0; i < 9; i++) wg[i] = __ldg(wp + i);
        const int par = c & 1;
        float acc = __ldg(conv_b + c);
        #pragma unroll
        for (int r = 0; r < 3; r++) {
            int hh = h + r - 1;
            if (hh < 0 || hh >= 128) continue;
            const float* xrow = xp + (size_t)hh * 128;
            const float* pfr = pf_sm + par * 384 + r * 128;
            #pragma unroll
            for (int s = 0; s < 3; s++) {
                int ww = w + s - 1;
                if (ww < 0 || ww >= 128) continue;
                acc += (__ldg(xrow + ww) + pfr[ww]) * wg[r * 3 + s];
            }
        }
        e_sm[c * 129 + w] = acc;
    }
    __syncthreads();

    // stage 2: LN stats per token (column w)
    if (tid < 128) {
        int wi = tid;
        float s1 = 0.f, s2 = 0.f;
        #pragma unroll 8
        for (int c = 0; c < 128; c++) {
            float v = e_sm[c * 129 + wi];
            s1 += v; s2 += v * v;
        }
        float mu = s1 * (1.0f / 128.0f);
        float var = s2 * (1.0f / 128.0f) - mu * mu;
        stat[wi] = mu;
        stat[128 + wi] = rsqrtf(var + 1e-5f);
    }
    __syncthreads();

    // stage 3: normalize + write xf [B,N,C] (coalesced over c)
    const size_t base = ((size_t)b * Nn + (size_t)h * 128) * 128;
    for (int i = tid; i < 128 * 128; i += 256) {
        int wi = i >> 7, c = i & 127;
        float v = (e_sm[c * 129 + wi] - stat[wi]) * stat[128 + wi]
                  * __ldg(ln_g + c) + __ldg(ln_b + c);
        g_xf[base + (size_t)wi * 128 + c] = v;
    }
}

// =============================================================================
// SGEMM: Co[m,n] = sum_k A[m,k] * W[n,k]   (A:[M,128] row-major, W:[NCOLS,128])
// 128x128 block tile, BK=8, 256 threads, 8x8 microtile
// =============================================================================
template<int NCOLS, bool RELU_QK, bool HAS_BIAS>
__global__ void sgemm_kernel(const float* __restrict__ A,
                             const float* __restrict__ Wm,
                             const float* __restrict__ bias,
                             float* __restrict__ Co)
{
    __shared__ float As[8][128];
    __shared__ float Bs[8][128];
    const int K = 128;
    const int bm = blockIdx.y * 128;
    const int bn = blockIdx.x * 128;
    const int tid = threadIdx.x;           // 256
    const int a_row = tid >> 1;            // 0..127
    const int a_col = (tid & 1) * 4;       // 0 or 4
    const int tx = tid & 15;
    const int ty = tid >> 4;

    float acc[8][8];
    #pragma unroll
    for (int i = 0; i < 8; i++)
        #pragma unroll
        for (int j = 0; j < 8; j++) acc[i][j] = 0.f;

    for (int k0 = 0; k0 < K; k0 += 8) {
        float4 a4 = *(const float4*)(A  + (size_t)(bm + a_row) * K + k0 + a_col);
        float4 b4 = *(const float4*)(Wm + (size_t)(bn + a_row) * K + k0 + a_col);
        As[a_col + 0][a_row] = a4.x; As[a_col + 1][a_row] = a4.y;
        As[a_col + 2][a_row] = a4.z; As[a_col + 3][a_row] = a4.w;
        Bs[a_col + 0][a_row] = b4.x; Bs[a_col + 1][a_row] = b4.y;
        Bs[a_col + 2][a_row] = b4.z; Bs[a_col + 3][a_row] = b4.w;
        __syncthreads();
        #pragma unroll
        for (int kk = 0; kk < 8; kk++) {
            float4 a0 = *(const float4*)&As[kk][ty * 8];
            float4 a1 = *(const float4*)&As[kk][ty * 8 + 4];
            float4 b0 = *(const float4*)&Bs[kk][tx * 8];
            float4 b1 = *(const float4*)&Bs[kk][tx * 8 + 4];
            float ar[8] = {a0.x, a0.y, a0.z, a0.w, a1.x, a1.y, a1.z, a1.w};
            float br[8] = {b0.x, b0.y, b0.z, b0.w, b1.x, b1.y, b1.z, b1.w};
            #pragma unroll
            for (int i = 0; i < 8; i++)
                #pragma unroll
                for (int j = 0; j < 8; j++)
                    acc[i][j] += ar[i] * br[j];
        }
        __syncthreads();
    }

    #pragma unroll
    for (int i = 0; i < 8; i++) {
        const int m = bm + ty * 8 + i;
        #pragma unroll
        for (int jj = 0; jj < 8; jj += 4) {
            const int n = bn + tx * 8 + jj;
            float4 v = make_float4(acc[i][jj], acc[i][jj + 1],
                                   acc[i][jj + 2], acc[i][jj + 3]);
            if (HAS_BIAS) {
                v.x += __ldg(bias + n + 0); v.y += __ldg(bias + n + 1);
                v.z += __ldg(bias + n + 2); v.w += __ldg(bias + n + 3);
            }
            if (RELU_QK) {
                if (n < 256) {  // q and k parts get relu (256 is float4-aligned)
                    v.x = fmaxf(v.x, 0.f); v.y = fmaxf(v.y, 0.f);
                    v.z = fmaxf(v.z, 0.f); v.w = fmaxf(v.w, 0.f);
                }
            }
            *(float4*)(Co + (size_t)m * NCOLS + n) = v;
        }
    }
}

// =============================================================================
// context init + accumulate:  ctx[bh][d*16+e] = sum_n k[n,d]*v[n,e]
//                             ctx[bh][256+d]  = sum_n k[n,d]
// =============================================================================
__global__ void ctx_init_kernel()
{
    int i = blockIdx.x * blockDim.x + threadIdx.x;
    if (i < 64 * 272) g_ctx[i] = 0.f;
}

#define CTX_SPLIT 32   // chunks of N per (b,head)

__global__ void ctx_kernel()
{
    __shared__ float k_sm[32][16];
    __shared__ float v_sm[32][16];
    const int bh = blockIdx.y;              // 0..63
    const int b = bh >> 3, head = bh & 7;
    const int chunk = blockIdx.x;           // 0..CTX_SPLIT-1
    const int tid = threadIdx.x;            // 256
    const int d = tid >> 4, e = tid & 15;

    float cacc = 0.f, ksacc = 0.f;
    const size_t qbase = (size_t)b * Nn * 384 + 128 + head * 16;
    const int n0 = chunk * (Nn / CTX_SPLIT);        // 512 tokens per chunk

    for (int t0 = 0; t0 < Nn / CTX_SPLIT; t0 += 32) {
        const int tl = tid >> 4;            // 0..15
        const int dl = tid & 15;
        #pragma unroll
        for (int rep = 0; rep < 2; rep++) {
            int tok = tl + rep * 16;
            size_t off = qbase + (size_t)(n0 + t0 + tok) * 384 + dl;
            k_sm[tok][dl] = g_qkv[off];
            v_sm[tok][dl] = g_qkv[off + 128];
        }
        __syncthreads();
        #pragma unroll
        for (int t2 = 0; t2 < 32; t2++) {
            float kv = k_sm[t2][d];
            cacc += kv * v_sm[t2][e];
            if (e == 0) ksacc += kv;
        }
        __syncthreads();
    }
    atomicAdd(&g_ctx[bh * 272 + d * 16 + e], cacc);
    if (e == 0) atomicAdd(&g_ctx[bh * 272 + 256 + d], ksacc);
}

// =============================================================================
// apply: attn[m, head*16+e] = (sum_d q[m,d]*ctx[d,e]) / max(sum_d q[m,d]*ks[d], 1e-6)
// 128 threads, 16 tokens per block
// =============================================================================
__global__ void apply_kernel()
{
    __shared__ float ctx_s[8 * 272];
    __shared__ float q_sm[128];
    const int tid = threadIdx.x;            // 128
    const int m0 = blockIdx.x * 16;
    const int b = m0 >> 14;                 // / 16384

    for (int i = tid; i < 8 * 272; i += 128) ctx_s[i] = g_ctx[b * 8 * 272 + i];
    __syncthreads();

    const int head = tid >> 4, e = tid & 15;
    const float* crow = &ctx_s[head * 272];

    for (int t = 0; t < 16; t++) {
        const int m = m0 + t;
        q_sm[tid] = g_qkv[(size_t)m * 384 + tid];
        __syncthreads();
        float num = 0.f, den = 0.f;
        #pragma unroll
        for (int d2 = 0; d2 < 16; d2++) {
            float qd = q_sm[head * 16 + d2];
            num += qd * crow[d2 * 16 + e];
            den += qd * crow[256 + d2];
        }
        g_attn[(size_t)m * 128 + tid] = num / fmaxf(den, 1e-6f);
        __syncthreads();
    }
}

// =============================================================================
// final: out[b,c,n] = tmp[b,n,c] + x[b,c,n]    (32x32 smem transpose tiles)
// =============================================================================
__global__ void out_kernel(const float* __restrict__ x, float* __restrict__ out)
{
    __shared__ float tile[32][33];
    const int n0 = blockIdx.x * 32;
    const int c0 = blockIdx.y * 32;
    const int b = blockIdx.z;
    const int tx = threadIdx.x, ty = threadIdx.y;   // 32 x 8

    #pragma unroll
    for (int i = 0; i < 4; i++) {
        int n = n0 + ty + i * 8;
        tile[ty + i * 8][tx] = g_tmp[((size_t)b * Nn + n) * 128 + c0 + tx];
    }
    __syncthreads();
    #pragma unroll
    for (int i = 0; i < 4; i++) {
        int c = c0 + ty + i * 8;
        size_t idx = ((size_t)b * 128 + c) * (size_t)Nn + n0 + tx;
        out[idx] = tile[tx][ty + i * 8] + x[idx];
    }
}

// =============================================================================
// launch
// =============================================================================
extern "C" void kernel_launch(void* const* d_in, const int* in_sizes, int n_in,
                              void* d_out, int out_size)
{
    (void)in_sizes; (void)n_in; (void)out_size;
    const float* x      = (const float*)d_in[0];
    const float* qkv_w  = (const float*)d_in[1];
    const float* proj_w = (const float*)d_in[2];
    const float* proj_b = (const float*)d_in[3];
    const float* conv_w = (const float*)d_in[4];
    const float* conv_b = (const float*)d_in[5];
    const float* ln_g   = (const float*)d_in[6];
    const float* ln_b   = (const float*)d_in[7];
    float* out = (float*)d_out;

    // device scratch pointers (host API, not stream ops; safe under capture)
    void *p_xf, *p_qkv, *p_attn, *p_tmp;
    cudaGetSymbolAddress(&p_xf,   g_xf);
    cudaGetSymbolAddress(&p_qkv,  g_qkv);
    cudaGetSymbolAddress(&p_attn, g_attn);
    cudaGetSymbolAddress(&p_tmp,  g_tmp);

    cudaFuncSetAttribute(conv_ln_kernel,
                         cudaFuncAttributeMaxDynamicSharedMemorySize, SMEM_A);

    // 1) posfeat + conv + LN -> g_xf [B,N,C]
    conv_ln_kernel<<<dim3(Hh, Bq), 256, SMEM_A>>>(x, conv_w, conv_b, ln_g, ln_b);

    // 2) QKV GEMM (+relu on q,k) -> g_qkv [M,384]
    sgemm_kernel<384, true, false><<<dim3(3, Mtot / 128), 256>>>(
        (const float*)p_xf, qkv_w, nullptr, (float*)p_qkv);

    // 3) context reduction
    ctx_init_kernel<<<(64 * 272 + 255) / 256, 256>>>();
    ctx_kernel<<<dim3(CTX_SPLIT, Bq * NHh), 256>>>();

    // 4) apply attention -> g_attn [M,128]
    apply_kernel<<<Mtot / 16, 128>>>();

    // 5) proj GEMM + bias -> g_tmp [M,128]
    sgemm_kernel<128, false, true><<<dim3(1, Mtot / 128), 256>>>(
        (const float*)p_attn, proj_w, proj_b, (float*)p_tmp);

    // 6) transpose + residual -> out [B,C,H,W]
    out_kernel<<<dim3(Nn / 32, Cc / 32, Bq), dim3(32, 8)>>>(x, out);
}

// round 2
// speedup vs baseline: 1.3904x; 1.3904x over previous
#include <cuda_runtime.h>
#include <math.h>
#include <stdint.h>

// Problem constants
#define Bq   8
#define Cc   128
#define Hh   128
#define Wd   128
#define Nn   16384          // H*W
#define NHh  8
#define HDd  16
#define Mtot (Bq * Nn)      // 131072

#define PI_F 3.14159265358979f

// ---------------- scratch (static device arrays; no allocations) -------------
__device__ float g_xf[(size_t)Mtot * Cc];        // [B,N,C] post-LN          64 MB
__device__ float g_qkv[(size_t)Mtot * 3 * Cc];   // [B,N,3C]                192 MB
__device__ float g_ctx[64 * 272];                // per (b,head): 256 ctx + 16 ksum
__device__ float g_meff[8 * 128 * 128];          // per-b fused ctx@projW^T

// ---------------- tf32 helpers ----------------------------------------------
__device__ __forceinline__ uint32_t f2tf32(float f) {
    uint32_t o;
    asm("cvt.rna.tf32.f32 %0, %1;" : "=r"(o) : "f"(f));
    return o;
}

__device__ __forceinline__ void mma_tf32(float* d, const uint32_t* a, const uint32_t* b) {
    asm volatile(
        "mma.sync.aligned.m16n8k8.row.col.f32.tf32.tf32.f32 "
        "{%0,%1,%2,%3}, {%4,%5,%6,%7}, {%8,%9}, {%0,%1,%2,%3};"
        : "+f"(d[0]), "+f"(d[1]), "+f"(d[2]), "+f"(d[3])
        : "r"(a[0]), "r"(a[1]), "r"(a[2]), "r"(a[3]),
          "r"(b[0]), "r"(b[1]));
}

// =============================================================================
// Kernel A: polar features + depthwise 3x3 conv + channel LayerNorm
// block = (b,h) row; 256 threads; writes xf in [B,N,C]
// =============================================================================
#define SMEM_A ((128 * 129 + 2 * 3 * 128 + 256) * 4)

__global__ void conv_ln_kernel(const float* __restrict__ x,
                               const float* __restrict__ conv_w,
                               const float* __restrict__ conv_b,
                               const float* __restrict__ ln_g,
                               const float* __restrict__ ln_b)
{
    extern __shared__ float sm[];
    float* e_sm = sm;                       // [128][129]
    float* pf_sm = sm + 128 * 129;          // [2][3][128]
    float* stat = pf_sm + 2 * 3 * 128;      // mu[128], rinv[128]

    const int h = blockIdx.x;
    const int b = blockIdx.y;
    const int tid = threadIdx.x;            // 256

    for (int i = tid; i < 3 * 128; i += 256) {
        int r = i >> 7, w = i & 127;
        float yc = (float)(h + r - 1 - 64);
        float xc = (float)(w - 64);
        float rho = sqrtf(xc * xc + yc * yc) * (1.0f / 64.0f);
        float th  = (atan2f(yc, xc) + PI_F) * (1.0f / (2.0f * PI_F));
        pf_sm[0 * 384 + i] = rho;   // even channels
        pf_sm[1 * 384 + i] = th;    // odd channels
    }
    __syncthreads();

    const int w = tid & 127;
    const int sub = tid >> 7;
    for (int c = sub; c < 128; c += 2) {
        const float* xp = x + ((size_t)b * 128 + c) * (size_t)Nn;
        const float* wp = conv_w + c * 9;
        float wg[9];
        #pragma unroll
        for (int i = 0; i < 9; i++) wg[i] = __ldg(wp + i);
        const int par = c & 1;
        float acc = __ldg(conv_b + c);
        #pragma unroll
        for (int r = 0; r < 3; r++) {
            int hh = h + r - 1;
            if (hh < 0 || hh >= 128) continue;
            const float* xrow = xp + (size_t)hh * 128;
            const float* pfr = pf_sm + par * 384 + r * 128;
            #pragma unroll
            for (int s = 0; s < 3; s++) {
                int ww = w + s - 1;
                if (ww < 0 || ww >= 128) continue;
                acc += (__ldg(xrow + ww) + pfr[ww]) * wg[r * 3 + s];
            }
        }
        e_sm[c * 129 + w] = acc;
    }
    __syncthreads();

    if (tid < 128) {
        int wi = tid;
        float s1 = 0.f, s2 = 0.f;
        #pragma unroll 8
        for (int c = 0; c < 128; c++) {
            float v = e_sm[c * 129 + wi];
            s1 += v; s2 += v * v;
        }
        float mu = s1 * (1.0f / 128.0f);
        float var = s2 * (1.0f / 128.0f) - mu * mu;
        stat[wi] = mu;
        stat[128 + wi] = rsqrtf(var + 1e-5f);
    }
    __syncthreads();

    const size_t base = ((size_t)b * Nn + (size_t)h * 128) * 128;
    for (int i = tid; i < 128 * 128; i += 256) {
        int wi = i >> 7, c = i & 127;
        float v = (e_sm[c * 129 + wi] - stat[wi]) * stat[128 + wi]
                  * __ldg(ln_g + c) + __ldg(ln_b + c);
        g_xf[base + (size_t)wi * 128 + c] = v;
    }
}

// =============================================================================
// QKV GEMM (tf32 mma): g_qkv[m, bx*128+n] = sum_k g_xf[m,k]*qkv_w[bx*128+n,k]
// relu on bx<2 (q,k). 128x128 tile, full K=128 in smem. 256 threads.
// =============================================================================
#define ASTRIDE 132
#define SMEM_QKV (2 * 128 * ASTRIDE * 4)

__global__ void qkv_mma_kernel(const float* __restrict__ Wm)
{
    extern __shared__ uint32_t smq[];
    uint32_t* As = smq;                     // [128][132] tf32
    uint32_t* Bs = smq + 128 * ASTRIDE;     // [128][132] tf32  (W rows)

    const int bx = blockIdx.x;              // 0..2 (q,k,v)
    const int bm = blockIdx.y * 128;
    const int tid = threadIdx.x;

    // cooperative load + cvt
    #pragma unroll
    for (int i = 0; i < 16; i++) {
        int f4 = i * 256 + tid;
        int r = f4 >> 5, c = (f4 & 31) * 4;
        float4 a4 = *(const float4*)(g_xf + (size_t)(bm + r) * 128 + c);
        As[r * ASTRIDE + c + 0] = f2tf32(a4.x);
        As[r * ASTRIDE + c + 1] = f2tf32(a4.y);
        As[r * ASTRIDE + c + 2] = f2tf32(a4.z);
        As[r * ASTRIDE + c + 3] = f2tf32(a4.w);
        float4 b4 = *(const float4*)(Wm + (size_t)(bx * 128 + r) * 128 + c);
        Bs[r * ASTRIDE + c + 0] = f2tf32(b4.x);
        Bs[r * ASTRIDE + c + 1] = f2tf32(b4.y);
        Bs[r * ASTRIDE + c + 2] = f2tf32(b4.z);
        Bs[r * ASTRIDE + c + 3] = f2tf32(b4.w);
    }
    __syncthreads();

    const int lane = tid & 31, warp = tid >> 5;
    const int wm = warp >> 1, wn = warp & 1;        // warp tile 32x64
    const int g = lane >> 2, tg = lane & 3;

    float acc[2][8][4];
    #pragma unroll
    for (int mm = 0; mm < 2; mm++)
        #pragma unroll
        for (int nn = 0; nn < 8; nn++)
            #pragma unroll
            for (int q = 0; q < 4; q++) acc[mm][nn][q] = 0.f;

    #pragma unroll
    for (int ks = 0; ks < 16; ks++) {
        const int k0 = ks * 8;
        uint32_t af[2][4], bf[8][2];
        #pragma unroll
        for (int mm = 0; mm < 2; mm++) {
            int r = wm * 32 + mm * 16 + g;
            af[mm][0] = As[(r) * ASTRIDE + k0 + tg];
            af[mm][1] = As[(r + 8) * ASTRIDE + k0 + tg];
            af[mm][2] = As[(r) * ASTRIDE + k0 + tg + 4];
            af[mm][3] = As[(r + 8) * ASTRIDE + k0 + tg + 4];
        }
        #pragma unroll
        for (int nn = 0; nn < 8; nn++) {
            int nc = wn * 64 + nn * 8 + g;
            bf[nn][0] = Bs[nc * ASTRIDE + k0 + tg];
            bf[nn][1] = Bs[nc * ASTRIDE + k0 + tg + 4];
        }
        #pragma unroll
        for (int mm = 0; mm < 2; mm++)
            #pragma unroll
            for (int nn = 0; nn < 8; nn++)
                mma_tf32(acc[mm][nn], af[mm], bf[nn]);
    }

    const bool relu = (bx < 2);
    #pragma unroll
    for (int mm = 0; mm < 2; mm++) {
        #pragma unroll
        for (int nn = 0; nn < 8; nn++) {
            int row = bm + wm * 32 + mm * 16 + g;
            int col = bx * 128 + wn * 64 + nn * 8 + 2 * tg;
            float2 v0 = make_float2(acc[mm][nn][0], acc[mm][nn][1]);
            float2 v1 = make_float2(acc[mm][nn][2], acc[mm][nn][3]);
            if (relu) {
                v0.x = fmaxf(v0.x, 0.f); v0.y = fmaxf(v0.y, 0.f);
                v1.x = fmaxf(v1.x, 0.f); v1.y = fmaxf(v1.y, 0.f);
            }
            *(float2*)(g_qkv + (size_t)row * 384 + col) = v0;
            *(float2*)(g_qkv + (size_t)(row + 8) * 384 + col) = v1;
        }
    }
}

// =============================================================================
// context: ctx[bh][d*16+e] = sum_n k[n,d]*v[n,e];  ctx[bh][256+d] = sum_n k[n,d]
// 4-way ILP accumulators, 64-token stages, float4 loads.
// =============================================================================
__global__ void ctx_init_kernel()
{
    int i = blockIdx.x * blockDim.x + threadIdx.x;
    if (i < 64 * 272) g_ctx[i] = 0.f;
}

#define CTX_SPLIT 32

__global__ void ctx_kernel()
{
    __shared__ float k_sm[64][16];
    __shared__ float v_sm[64][16];
    const int bh = blockIdx.y;
    const int b = bh >> 3, head = bh & 7;
    const int chunk = blockIdx.x;
    const int tid = threadIdx.x;            // 256
    const int d = tid >> 4, e = tid & 15;
    const int tok = tid >> 2, quad = tid & 3;

    const size_t qbase = (size_t)b * Nn * 384 + 128 + head * 16;
    const int n0 = chunk * (Nn / CTX_SPLIT);        // 512 tokens

    float c0 = 0.f, c1 = 0.f, c2 = 0.f, c3 = 0.f;
    float s0 = 0.f, s1 = 0.f, s2 = 0.f, s3 = 0.f;

    for (int t0 = 0; t0 < Nn / CTX_SPLIT; t0 += 64) {
        size_t off = qbase + (size_t)(n0 + t0 + tok) * 384 + quad * 4;
        float4 kv = *(const float4*)(g_qkv + off);
        float4 vv = *(const float4*)(g_qkv + off + 128);
        *(float4*)&k_sm[tok][quad * 4] = kv;
        *(float4*)&v_sm[tok][quad * 4] = vv;
        __syncthreads();
        #pragma unroll
        for (int t2 = 0; t2 < 64; t2 += 4) {
            float k0v = k_sm[t2 + 0][d];
            float k1v = k_sm[t2 + 1][d];
            float k2v = k_sm[t2 + 2][d];
            float k3v = k_sm[t2 + 3][d];
            c0 += k0v * v_sm[t2 + 0][e];  s0 += k0v;
            c1 += k1v * v_sm[t2 + 1][e];  s1 += k1v;
            c2 += k2v * v_sm[t2 + 2][e];  s2 += k2v;
            c3 += k3v * v_sm[t2 + 3][e];  s3 += k3v;
        }
        __syncthreads();
    }
    atomicAdd(&g_ctx[bh * 272 + d * 16 + e], (c0 + c1) + (c2 + c3));
    if (e == 0)
        atomicAdd(&g_ctx[bh * 272 + 256 + d], (s0 + s1) + (s2 + s3));
}

// =============================================================================
// Meff[b][n][c] = sum_e ctx[b, h(n)][d(n)][e] * proj_w[c][h*16+e]
// =============================================================================
__global__ void meff_kernel(const float* __restrict__ proj_w)
{
    __shared__ float ctx_s[8 * 272];
    const int b = blockIdx.x;
    const int tid = threadIdx.x;            // 256
    for (int i = tid; i < 8 * 272; i += 256) ctx_s[i] = g_ctx[b * 8 * 272 + i];
    __syncthreads();
    for (int i = tid; i < 128 * 128; i += 256) {
        int n = i >> 7, c = i & 127;
        int h = n >> 4, dd = n & 15;
        const float* cr = &ctx_s[h * 272 + dd * 16];
        const float* pw = proj_w + c * 128 + h * 16;
        float s = 0.f;
        #pragma unroll
        for (int ee = 0; ee < 16; ee++) s += cr[ee] * __ldg(pw + ee);
        g_meff[(size_t)b * 16384 + n * 128 + c] = s;
    }
}

// =============================================================================
// Fused kernel: per 128-token tile:
//   q'[t,n] = q[t,n] * 1/max(q[t,:]_h . ksum_h, 1e-6)      (per-head dinv)
//   out128[t,c] = q' @ Meff[b] + proj_b
//   out[b,c,n0+t] = out128[t,c] + x[b,c,n0+t]              (transpose+residual)
// =============================================================================
#define BSTRIDE 136
#define TSTRIDE 129
#define SMEM_K4 ((128 * ASTRIDE + 128 * BSTRIDE + 128 + 1024) * 4)

__global__ void fused_proj_kernel(const float* __restrict__ x,
                                  const float* __restrict__ proj_b,
                                  float* __restrict__ out)
{
    extern __shared__ uint32_t sm4[];
    uint32_t* As = sm4;                          // [128][132]: raw q, then tf32 q'
    uint32_t* Bs = sm4 + 128 * ASTRIDE;          // [128][136]: Meff tf32 ([n][c])
    float* ksum_s = (float*)(Bs + 128 * BSTRIDE);  // [128]
    float* dinv_s = ksum_s + 128;                  // [128][8]
    float* ts = (float*)sm4;                       // [128][129] epilogue reuse

    const int tid = threadIdx.x;            // 256
    const int m0 = blockIdx.x * 128;
    const int b = blockIdx.x >> 7;          // 128 tiles per batch

    // stage q (raw) and Meff (tf32)
    #pragma unroll
    for (int i = 0; i < 16; i++) {
        int f4 = i * 256 + tid;
        int r = f4 >> 5, c = (f4 & 31) * 4;
        float4 a4 = *(const float4*)(g_qkv + (size_t)(m0 + r) * 384 + c);
        As[r * ASTRIDE + c + 0] = __float_as_uint(a4.x);
        As[r * ASTRIDE + c + 1] = __float_as_uint(a4.y);
        As[r * ASTRIDE + c + 2] = __float_as_uint(a4.z);
        As[r * ASTRIDE + c + 3] = __float_as_uint(a4.w);
        float4 b4 = *(const float4*)(g_meff + (size_t)b * 16384 + (size_t)r * 128 + c);
        Bs[r * BSTRIDE + c + 0] = f2tf32(b4.x);
        Bs[r * BSTRIDE + c + 1] = f2tf32(b4.y);
        Bs[r * BSTRIDE + c + 2] = f2tf32(b4.z);
        Bs[r * BSTRIDE + c + 3] = f2tf32(b4.w);
    }
    if (tid < 128) {
        int h = tid >> 4, dd = tid & 15;
        ksum_s[tid] = g_ctx[(b * 8 + h) * 272 + 256 + dd];
    }
    __syncthreads();

    // per-token per-head denominator
    if (tid < 128) {
        const int t = tid;
        #pragma unroll
        for (int h = 0; h < 8; h++) {
            float den = 0.f;
            #pragma unroll
            for (int dd = 0; dd < 16; dd++)
                den += __uint_as_float(As[t * ASTRIDE + h * 16 + dd]) * ksum_s[h * 16 + dd];
            dinv_s[t * 8 + h] = 1.0f / fmaxf(den, 1e-6f);
        }
    }
    __syncthreads();

    // scale + cvt in place
    #pragma unroll
    for (int i = 0; i < 64; i++) {
        int idx = i * 256 + tid;
        int t = idx >> 7, c = idx & 127;
        float v = __uint_as_float(As[t * ASTRIDE + c]) * dinv_s[t * 8 + (c >> 4)];
        As[t * ASTRIDE + c] = f2tf32(v);
    }
    __syncthreads();

    // GEMM q'[128x128] @ Meff^T-ish -> out128[128x128]
    const int lane = tid & 31, warp = tid >> 5;
    const int wm = warp >> 1, wn = warp & 1;
    const int g = lane >> 2, tg = lane & 3;

    float acc[2][8][4];
    #pragma unroll
    for (int mm = 0; mm < 2; mm++)
        #pragma unroll
        for (int nn = 0; nn < 8; nn++)
            #pragma unroll
            for (int q = 0; q < 4; q++) acc[mm][nn][q] = 0.f;

    #pragma unroll
    for (int ks = 0; ks < 16; ks++) {
        const int k0 = ks * 8;
        uint32_t af[2][4], bf[8][2];
        #pragma unroll
        for (int mm = 0; mm < 2; mm++) {
            int r = wm * 32 + mm * 16 + g;
            af[mm][0] = As[(r) * ASTRIDE + k0 + tg];
            af[mm][1] = As[(r + 8) * ASTRIDE + k0 + tg];
            af[mm][2] = As[(r) * ASTRIDE + k0 + tg + 4];
            af[mm][3] = As[(r + 8) * ASTRIDE + k0 + tg + 4];
        }
        #pragma unroll
        for (int nn = 0; nn < 8; nn++) {
            int nc = wn * 64 + nn * 8 + g;
            bf[nn][0] = Bs[(k0 + tg) * BSTRIDE + nc];
            bf[nn][1] = Bs[(k0 + tg + 4) * BSTRIDE + nc];
        }
        #pragma unroll
        for (int mm = 0; mm < 2; mm++)
            #pragma unroll
            for (int nn = 0; nn < 8; nn++)
                mma_tf32(acc[mm][nn], af[mm], bf[nn]);
    }
    __syncthreads();   // all smem reads done; reuse as transpose buffer

    // write fragments (+bias) into ts [token][c] stride 129
    #pragma unroll
    for (int mm = 0; mm < 2; mm++) {
        #pragma unroll
        for (int nn = 0; nn < 8; nn++) {
            int row = wm * 32 + mm * 16 + g;
            int col = wn * 64 + nn * 8 + 2 * tg;
            float b0 = __ldg(proj_b + col), b1 = __ldg(proj_b + col + 1);
            ts[row * TSTRIDE + col]           = acc[mm][nn][0] + b0;
            ts[row * TSTRIDE + col + 1]       = acc[mm][nn][1] + b1;
            ts[(row + 8) * TSTRIDE + col]     = acc[mm][nn][2] + b0;
            ts[(row + 8) * TSTRIDE + col + 1] = acc[mm][nn][3] + b1;
        }
    }
    __syncthreads();

    // out[b,c,n0+t] = ts[t][c] + x[b,c,n0+t]   (coalesced over t)
    const int n0 = (blockIdx.x & 127) * 128;
    #pragma unroll
    for (int i = 0; i < 64; i++) {
        int idx = i * 256 + tid;
        int c = idx >> 7, t = idx & 127;
        size_t gidx = ((size_t)b * 128 + c) * (size_t)Nn + n0 + t;
        out[gidx] = ts[t * TSTRIDE + c] + x[gidx];
    }
}

// =============================================================================
// launch
// =============================================================================
extern "C" void kernel_launch(void* const* d_in, const int* in_sizes, int n_in,
                              void* d_out, int out_size)
{
    (void)in_sizes; (void)n_in; (void)out_size;
    const float* x      = (const float*)d_in[0];
    const float* qkv_w  = (const float*)d_in[1];
    const float* proj_w = (const float*)d_in[2];
    const float* proj_b = (const float*)d_in[3];
    const float* conv_w = (const float*)d_in[4];
    const float* conv_b = (const float*)d_in[5];
    const float* ln_g   = (const float*)d_in[6];
    const float* ln_b   = (const float*)d_in[7];
    float* out = (float*)d_out;

    cudaFuncSetAttribute(conv_ln_kernel,
                         cudaFuncAttributeMaxDynamicSharedMemorySize, SMEM_A);
    cudaFuncSetAttribute(qkv_mma_kernel,
                         cudaFuncAttributeMaxDynamicSharedMemorySize, SMEM_QKV);
    cudaFuncSetAttribute(fused_proj_kernel,
                         cudaFuncAttributeMaxDynamicSharedMemorySize, SMEM_K4);

    // 1) posfeat + conv + LN -> g_xf [B,N,C]
    conv_ln_kernel<<<dim3(Hh, Bq), 256, SMEM_A>>>(x, conv_w, conv_b, ln_g, ln_b);

    // 2) QKV GEMM (tf32 mma, relu on q,k) -> g_qkv [M,384]
    qkv_mma_kernel<<<dim3(3, Mtot / 128), 256, SMEM_QKV>>>(qkv_w);

    // 3) context reduction
    ctx_init_kernel<<<(64 * 272 + 255) / 256, 256>>>();
    ctx_kernel<<<dim3(CTX_SPLIT, Bq * NHh), 256>>>();

    // 4) fold ctx into proj weights: Meff[b] = blockdiag(ctx) @ proj_w^T
    meff_kernel<<<8, 256>>>(proj_w);

    // 5) fused dinv-scale + proj GEMM + bias + transpose + residual -> out
    fused_proj_kernel<<<Mtot / 128, 256, SMEM_K4>>>(x, proj_b, out);
}

// round 4
// speedup vs baseline: 1.7084x; 1.2287x over previous
#include <cuda_runtime.h>
#include <math.h>
#include <stdint.h>

// Problem constants
#define Bq   8
#define Cc   128
#define Hh   128
#define Wd   128
#define Nn   16384          // H*W
#define NHh  8
#define HDd  16
#define Mtot (Bq * Nn)      // 131072

#define PI_F 3.14159265358979f

// ---------------- scratch (static device arrays; no allocations) -------------
__device__ float g_xf[(size_t)Mtot * Cc];          // [B,N,C] post-LN, tf32 bits  64 MB
__device__ float g_q[(size_t)Mtot * Cc];           // [B,N,C] relu(q)             64 MB
__device__ float g_ctx_part[8 * 64 * 272];         // 8-way split ctx partials
__device__ float g_ksum[64 * 16];                  // final ksum per (b,head)
__device__ float g_meff[8 * 128 * 128];            // per-b fused ctx@projW^T

// ---------------- tf32 helpers ----------------------------------------------
__device__ __forceinline__ uint32_t f2tf32(float f) {
    uint32_t o;
    asm("cvt.rna.tf32.f32 %0, %1;" : "=r"(o) : "f"(f));
    return o;
}

__device__ __forceinline__ void mma_tf32(float* d, const uint32_t* a, const uint32_t* b) {
    asm volatile(
        "mma.sync.aligned.m16n8k8.row.col.f32.tf32.tf32.f32 "
        "{%0,%1,%2,%3}, {%4,%5,%6,%7}, {%8,%9}, {%0,%1,%2,%3};"
        : "+f"(d[0]), "+f"(d[1]), "+f"(d[2]), "+f"(d[3])
        : "r"(a[0]), "r"(a[1]), "r"(a[2]), "r"(a[3]),
          "r"(b[0]), "r"(b[1]));
}

// =============================================================================
// Kernel A: polar features + depthwise 3x3 conv + channel LayerNorm
// block = (b,h) row; 256 threads; stages (x+pf) rows in smem (3 LDG per chan),
// writes xf in [B,N,C] as tf32 bit-patterns.
// =============================================================================
#define CLN_ESM   0                      // e_sm [128][129]
#define CLN_PF    (128 * 129)            // pf   [2][3][128]
#define CLN_STAT  (CLN_PF + 768)         // stats [256]
#define CLN_XS    (CLN_STAT + 256)       // sm_x [2][3][130]
#define SMEM_A    ((CLN_XS + 2 * 3 * 130) * 4)

__global__ void conv_ln_kernel(const float* __restrict__ x,
                               const float* __restrict__ conv_w,
                               const float* __restrict__ conv_b,
                               const float* __restrict__ ln_g,
                               const float* __restrict__ ln_b)
{
    extern __shared__ float sm[];
    float* e_sm  = sm + CLN_ESM;
    float* pf_sm = sm + CLN_PF;
    float* stat  = sm + CLN_STAT;
    float* sm_x  = sm + CLN_XS;

    const int h = blockIdx.x;
    const int b = blockIdx.y;
    const int tid = threadIdx.x;            // 256
    const int w = tid & 127;
    const int sub = tid >> 7;               // 0/1 -> channel parity

    for (int i = tid; i < 3 * 128; i += 256) {
        int r = i >> 7, ww = i & 127;
        float yc = (float)(h + r - 1 - 64);
        float xc = (float)(ww - 64);
        float rho = sqrtf(xc * xc + yc * yc) * (1.0f / 64.0f);
        float th  = (atan2f(yc, xc) + PI_F) * (1.0f / (2.0f * PI_F));
        pf_sm[0 * 384 + i] = rho;   // even channels
        pf_sm[1 * 384 + i] = th;    // odd channels
    }
    if (tid < 6) {                          // zero halo columns once
        int ss = tid / 3, rr = tid % 3;
        sm_x[ss * 390 + rr * 130 + 0] = 0.f;
        sm_x[ss * 390 + rr * 130 + 129] = 0.f;
    }
    __syncthreads();

    for (int cp = 0; cp < 64; cp++) {
        const int c = cp * 2 + sub;
        const float* wp = conv_w + c * 9;
        float wg[9];
        #pragma unroll
        for (int i = 0; i < 9; i++) wg[i] = __ldg(wp + i);

        // stage x + pf rows (zero outside image)
        #pragma unroll
        for (int r = 0; r < 3; r++) {
            int hh = h + r - 1;
            float v = 0.f;
            if (hh >= 0 && hh < 128)
                v = __ldg(x + ((size_t)(b * 128 + c) * Nn) + hh * 128 + w)
                    + pf_sm[sub * 384 + r * 128 + w];
            sm_x[sub * 390 + r * 130 + (w + 1)] = v;
        }
        __syncthreads();

        float acc = __ldg(conv_b + c);
        #pragma unroll
        for (int r = 0; r < 3; r++)
            #pragma unroll
            for (int s = 0; s < 3; s++)
                acc += sm_x[sub * 390 + r * 130 + (w + s)] * wg[r * 3 + s];
        e_sm[c * 129 + w] = acc;
        __syncthreads();
    }

    if (tid < 128) {
        int wi = tid;
        float s1 = 0.f, s2 = 0.f;
        #pragma unroll 8
        for (int c = 0; c < 128; c++) {
            float v = e_sm[c * 129 + wi];
            s1 += v; s2 += v * v;
        }
        float mu = s1 * (1.0f / 128.0f);
        float var = s2 * (1.0f / 128.0f) - mu * mu;
        stat[wi] = mu;
        stat[128 + wi] = rsqrtf(var + 1e-5f);
    }
    __syncthreads();

    const size_t base = ((size_t)b * Nn + (size_t)h * 128) * 128;
    for (int i = tid; i < 128 * 128; i += 256) {
        int wi = i >> 7, c = i & 127;
        float v = (e_sm[c * 129 + wi] - stat[wi]) * stat[128 + wi]
                  * __ldg(ln_g + c) + __ldg(ln_b + c);
        g_xf[base + (size_t)wi * 128 + c] = __uint_as_float(f2tf32(v));
    }
}

// =============================================================================
// zero context partials
// =============================================================================
__global__ void ctx_zero_kernel()
{
    int i = blockIdx.x * blockDim.x + threadIdx.x;
    if (i < 8 * 64 * 272) g_ctx_part[i] = 0.f;
}

// =============================================================================
// Fused QKV GEMM + context:
//   per 128-token tile: A (xf, tf32) resident; loop g in {q,k,v}:
//     load W_g -> GEMM -> epilogue (q: relu->global; k: relu->smem; v: ->smem)
//   then accumulate per-head 16x16 ctx + ksum from smem k,v -> atomics.
// =============================================================================
#define ASTRIDE 132
#define QC_AS 0
#define QC_WS (128 * ASTRIDE)            // W (tf32); reused as v (fp32) later
#define QC_KS (2 * 128 * ASTRIDE)        // k (fp32)
#define SMEM_QC (3 * 128 * ASTRIDE * 4)  // 202752 B

__global__ void qkvctx_kernel(const float* __restrict__ Wm)
{
    extern __shared__ uint32_t smq[];
    uint32_t* As = smq + QC_AS;
    uint32_t* Ws = smq + QC_WS;
    float* ks_f = (float*)(smq + QC_KS);
    float* vs_f = (float*)(smq + QC_WS);

    const int tid = threadIdx.x;            // 256
    const int bm = blockIdx.x * 128;
    const int b  = blockIdx.x >> 7;         // 128 tiles per batch
    const int lane = tid & 31, warp = tid >> 5;
    const int wm = warp >> 1, wn = warp & 1;
    const int g = lane >> 2, tg = lane & 3;

    // load A (already tf32 bits)
    #pragma unroll
    for (int i = 0; i < 16; i++) {
        int f4 = i * 256 + tid;
        int r = f4 >> 5, c = (f4 & 31) * 4;
        uint4 a4 = *(const uint4*)(g_xf + (size_t)(bm + r) * 128 + c);
        As[r * ASTRIDE + c + 0] = a4.x; As[r * ASTRIDE + c + 1] = a4.y;
        As[r * ASTRIDE + c + 2] = a4.z; As[r * ASTRIDE + c + 3] = a4.w;
    }

    for (int grp = 0; grp < 3; grp++) {
        // load W group (cvt to tf32). First iter: no pending readers of Ws.
        #pragma unroll
        for (int i = 0; i < 16; i++) {
            int f4 = i * 256 + tid;
            int r = f4 >> 5, c = (f4 & 31) * 4;
            float4 b4 = *(const float4*)(Wm + (size_t)(grp * 128 + r) * 128 + c);
            Ws[r * ASTRIDE + c + 0] = f2tf32(b4.x);
            Ws[r * ASTRIDE + c + 1] = f2tf32(b4.y);
            Ws[r * ASTRIDE + c + 2] = f2tf32(b4.z);
            Ws[r * ASTRIDE + c + 3] = f2tf32(b4.w);
        }
        __syncthreads();

        float acc[2][8][4];
        #pragma unroll
        for (int mm = 0; mm < 2; mm++)
            #pragma unroll
            for (int nn = 0; nn < 8; nn++)
                #pragma unroll
                for (int q = 0; q < 4; q++) acc[mm][nn][q] = 0.f;

        #pragma unroll
        for (int kk = 0; kk < 16; kk++) {
            const int k0 = kk * 8;
            uint32_t af[2][4], bf[8][2];
            #pragma unroll
            for (int mm = 0; mm < 2; mm++) {
                int r = wm * 32 + mm * 16 + g;
                af[mm][0] = As[(r) * ASTRIDE + k0 + tg];
                af[mm][1] = As[(r + 8) * ASTRIDE + k0 + tg];
                af[mm][2] = As[(r) * ASTRIDE + k0 + tg + 4];
                af[mm][3] = As[(r + 8) * ASTRIDE + k0 + tg + 4];
            }
            #pragma unroll
            for (int nn = 0; nn < 8; nn++) {
                int nc = wn * 64 + nn * 8 + g;
                bf[nn][0] = Ws[nc * ASTRIDE + k0 + tg];
                bf[nn][1] = Ws[nc * ASTRIDE + k0 + tg + 4];
            }
            #pragma unroll
            for (int mm = 0; mm < 2; mm++)
                #pragma unroll
                for (int nn = 0; nn < 8; nn++)
                    mma_tf32(acc[mm][nn], af[mm], bf[nn]);
        }
        __syncthreads();   // GEMM reads of Ws done: safe to overwrite (v) / reload

        // epilogue
        #pragma unroll
        for (int mm = 0; mm < 2; mm++) {
            #pragma unroll
            for (int nn = 0; nn < 8; nn++) {
                int row = wm * 32 + mm * 16 + g;
                int col = wn * 64 + nn * 8 + 2 * tg;
                float v0 = acc[mm][nn][0], v1 = acc[mm][nn][1];
                float v2 = acc[mm][nn][2], v3 = acc[mm][nn][3];
                if (grp < 2) {   // relu for q,k
                    v0 = fmaxf(v0, 0.f); v1 = fmaxf(v1, 0.f);
                    v2 = fmaxf(v2, 0.f); v3 = fmaxf(v3, 0.f);
                }
                if (grp == 0) {
                    *(float2*)(g_q + (size_t)(bm + row) * 128 + col) = make_float2(v0, v1);
                    *(float2*)(g_q + (size_t)(bm + row + 8) * 128 + col) = make_float2(v2, v3);
                } else if (grp == 1) {
                    ks_f[row * ASTRIDE + col] = v0; ks_f[row * ASTRIDE + col + 1] = v1;
                    ks_f[(row + 8) * ASTRIDE + col] = v2; ks_f[(row + 8) * ASTRIDE + col + 1] = v3;
                } else {
                    vs_f[row * ASTRIDE + col] = v0; vs_f[row * ASTRIDE + col + 1] = v1;
                    vs_f[(row + 8) * ASTRIDE + col] = v2; vs_f[(row + 8) * ASTRIDE + col + 1] = v3;
                }
            }
        }
    }
    __syncthreads();   // k,v tiles complete

    // per-head ctx partials: head = warp; worker w owns [d0..d0+3]x[e0..e0+1]
    const int head = warp;
    const int wk = lane;
    const int d0 = (wk >> 3) * 4;
    const int e0 = (wk & 7) * 2;
    const int cb = head * 16;

    float ca[4][2];
    #pragma unroll
    for (int j = 0; j < 4; j++) { ca[j][0] = 0.f; ca[j][1] = 0.f; }
    float ksa[4] = {0.f, 0.f, 0.f, 0.f};

    #pragma unroll 4
    for (int t = 0; t < 128; t++) {
        float4 kq = *(const float4*)&ks_f[t * ASTRIDE + cb + d0];
        float2 vp = *(const float2*)&vs_f[t * ASTRIDE + cb + e0];
        ca[0][0] += kq.x * vp.x; ca[0][1] += kq.x * vp.y;
        ca[1][0] += kq.y * vp.x; ca[1][1] += kq.y * vp.y;
        ca[2][0] += kq.z * vp.x; ca[2][1] += kq.z * vp.y;
        ca[3][0] += kq.w * vp.x; ca[3][1] += kq.w * vp.y;
        if (e0 == 0) {
            ksa[0] += kq.x; ksa[1] += kq.y; ksa[2] += kq.z; ksa[3] += kq.w;
        }
    }

    const int slot = blockIdx.x & 7;
    float* part = g_ctx_part + ((size_t)slot * 64 + (b * 8 + head)) * 272;
    #pragma unroll
    for (int j = 0; j < 4; j++) {
        atomicAdd(&part[(d0 + j) * 16 + e0 + 0], ca[j][0]);
        atomicAdd(&part[(d0 + j) * 16 + e0 + 1], ca[j][1]);
    }
    if (e0 == 0) {
        #pragma unroll
        for (int j = 0; j < 4; j++)
            atomicAdd(&part[256 + d0 + j], ksa[j]);
    }
}

// =============================================================================
// meff: reduce 8 partial slots; Meff[b][n][c] = sum_e ctx[h(n)][d(n)][e]*proj_w[c][h*16+e]
// also writes g_ksum.
// =============================================================================
__global__ void meff_kernel(const float* __restrict__ proj_w)
{
    __shared__ float ctx_s[8 * 272];
    const int b = blockIdx.x;
    const int tid = threadIdx.x;            // 256
    for (int i = tid; i < 8 * 272; i += 256) {
        int hh = i / 272, j = i % 272;
        float s = 0.f;
        #pragma unroll
        for (int slot = 0; slot < 8; slot++)
            s += g_ctx_part[((size_t)slot * 64 + (b * 8 + hh)) * 272 + j];
        ctx_s[i] = s;
        if (j >= 256) g_ksum[b * 128 + hh * 16 + (j - 256)] = s;
    }
    __syncthreads();
    for (int i = tid; i < 128 * 128; i += 256) {
        int n = i >> 7, c = i & 127;
        int hh = n >> 4, dd = n & 15;
        const float* cr = &ctx_s[hh * 272 + dd * 16];
        const float* pw = proj_w + c * 128 + hh * 16;
        float s = 0.f;
        #pragma unroll
        for (int ee = 0; ee < 16; ee++) s += cr[ee] * __ldg(pw + ee);
        g_meff[(size_t)b * 16384 + n * 128 + c] = s;
    }
}

// =============================================================================
// Fused: dinv-scale q -> GEMM vs Meff[b] -> +bias -> transpose+residual -> out
// =============================================================================
#define BSTRIDE 136
#define TSTRIDE 129
#define SMEM_K4 ((128 * ASTRIDE + 128 * BSTRIDE + 128 + 1024) * 4)

__global__ void fused_proj_kernel(const float* __restrict__ x,
                                  const float* __restrict__ proj_b,
                                  float* __restrict__ out)
{
    extern __shared__ uint32_t sm4[];
    uint32_t* As = sm4;                          // [128][132]: raw q, then tf32 q'
    uint32_t* Bs = sm4 + 128 * ASTRIDE;          // [128][136]: Meff tf32 ([n][c])
    float* ksum_s = (float*)(Bs + 128 * BSTRIDE);  // [128]
    float* dinv_s = ksum_s + 128;                  // [128][8]
    float* ts = (float*)sm4;                       // [128][129] epilogue reuse

    const int tid = threadIdx.x;            // 256
    const int m0 = blockIdx.x * 128;
    const int b = blockIdx.x >> 7;

    #pragma unroll
    for (int i = 0; i < 16; i++) {
        int f4 = i * 256 + tid;
        int r = f4 >> 5, c = (f4 & 31) * 4;
        float4 a4 = *(const float4*)(g_q + (size_t)(m0 + r) * 128 + c);
        As[r * ASTRIDE + c + 0] = __float_as_uint(a4.x);
        As[r * ASTRIDE + c + 1] = __float_as_uint(a4.y);
        As[r * ASTRIDE + c + 2] = __float_as_uint(a4.z);
        As[r * ASTRIDE + c + 3] = __float_as_uint(a4.w);
        float4 b4 = *(const float4*)(g_meff + (size_t)b * 16384 + (size_t)r * 128 + c);
        Bs[r * BSTRIDE + c + 0] = f2tf32(b4.x);
        Bs[r * BSTRIDE + c + 1] = f2tf32(b4.y);
        Bs[r * BSTRIDE + c + 2] = f2tf32(b4.z);
        Bs[r * BSTRIDE + c + 3] = f2tf32(b4.w);
    }
    if (tid < 128) ksum_s[tid] = g_ksum[b * 128 + tid];
    __syncthreads();

    if (tid < 128) {
        const int t = tid;
        #pragma unroll
        for (int hh = 0; hh < 8; hh++) {
            float den = 0.f;
            #pragma unroll
            for (int dd = 0; dd < 16; dd++)
                den += __uint_as_float(As[t * ASTRIDE + hh * 16 + dd]) * ksum_s[hh * 16 + dd];
            dinv_s[t * 8 + hh] = 1.0f / fmaxf(den, 1e-6f);
        }
    }
    __syncthreads();

    #pragma unroll
    for (int i = 0; i < 64; i++) {
        int idx = i * 256 + tid;
        int t = idx >> 7, c = idx & 127;
        float v = __uint_as_float(As[t * ASTRIDE + c]) * dinv_s[t * 8 + (c >> 4)];
        As[t * ASTRIDE + c] = f2tf32(v);
    }
    __syncthreads();

    const int lane = tid & 31, warp = tid >> 5;
    const int wm = warp >> 1, wn = warp & 1;
    const int g = lane >> 2, tg = lane & 3;

    float acc[2][8][4];
    #pragma unroll
    for (int mm = 0; mm < 2; mm++)
        #pragma unroll
        for (int nn = 0; nn < 8; nn++)
            #pragma unroll
            for (int q = 0; q < 4; q++) acc[mm][nn][q] = 0.f;

    #pragma unroll
    for (int kk = 0; kk < 16; kk++) {
        const int k0 = kk * 8;
        uint32_t af[2][4], bf[8][2];
        #pragma unroll
        for (int mm = 0; mm < 2; mm++) {
            int r = wm * 32 + mm * 16 + g;
            af[mm][0] = As[(r) * ASTRIDE + k0 + tg];
            af[mm][1] = As[(r + 8) * ASTRIDE + k0 + tg];
            af[mm][2] = As[(r) * ASTRIDE + k0 + tg + 4];
            af[mm][3] = As[(r + 8) * ASTRIDE + k0 + tg + 4];
        }
        #pragma unroll
        for (int nn = 0; nn < 8; nn++) {
            int nc = wn * 64 + nn * 8 + g;
            bf[nn][0] = Bs[(k0 + tg) * BSTRIDE + nc];
            bf[nn][1] = Bs[(k0 + tg + 4) * BSTRIDE + nc];
        }
        #pragma unroll
        for (int mm = 0; mm < 2; mm++)
            #pragma unroll
            for (int nn = 0; nn < 8; nn++)
                mma_tf32(acc[mm][nn], af[mm], bf[nn]);
    }
    __syncthreads();   // reuse smem as transpose buffer

    #pragma unroll
    for (int mm = 0; mm < 2; mm++) {
        #pragma unroll
        for (int nn = 0; nn < 8; nn++) {
            int row = wm * 32 + mm * 16 + g;
            int col = wn * 64 + nn * 8 + 2 * tg;
            float b0 = __ldg(proj_b + col), b1 = __ldg(proj_b + col + 1);
            ts[row * TSTRIDE + col]           = acc[mm][nn][0] + b0;
            ts[row * TSTRIDE + col + 1]       = acc[mm][nn][1] + b1;
            ts[(row + 8) * TSTRIDE + col]     = acc[mm][nn][2] + b0;
            ts[(row + 8) * TSTRIDE + col + 1] = acc[mm][nn][3] + b1;
        }
    }
    __syncthreads();

    const int n0 = (blockIdx.x & 127) * 128;
    #pragma unroll
    for (int i = 0; i < 64; i++) {
        int idx = i * 256 + tid;
        int c = idx >> 7, t = idx & 127;
        size_t gidx = ((size_t)b * 128 + c) * (size_t)Nn + n0 + t;
        out[gidx] = ts[t * TSTRIDE + c] + x[gidx];
    }
}

// =============================================================================
// launch
// =============================================================================
extern "C" void kernel_launch(void* const* d_in, const int* in_sizes, int n_in,
                              void* d_out, int out_size)
{
    (void)in_sizes; (void)n_in; (void)out_size;
    const float* x      = (const float*)d_in[0];
    const float* qkv_w  = (const float*)d_in[1];
    const float* proj_w = (const float*)d_in[2];
    const float* proj_b = (const float*)d_in[3];
    const float* conv_w = (const float*)d_in[4];
    const float* conv_b = (const float*)d_in[5];
    const float* ln_g   = (const float*)d_in[6];
    const float* ln_b   = (const float*)d_in[7];
    float* out = (float*)d_out;

    cudaFuncSetAttribute(conv_ln_kernel,
                         cudaFuncAttributeMaxDynamicSharedMemorySize, SMEM_A);
    cudaFuncSetAttribute(qkvctx_kernel,
                         cudaFuncAttributeMaxDynamicSharedMemorySize, SMEM_QC);
    cudaFuncSetAttribute(fused_proj_kernel,
                         cudaFuncAttributeMaxDynamicSharedMemorySize, SMEM_K4);

    // 1) posfeat + conv + LN -> g_xf [B,N,C] (tf32 bits)
    conv_ln_kernel<<<dim3(Hh, Bq), 256, SMEM_A>>>(x, conv_w, conv_b, ln_g, ln_b);

    // 2) zero ctx partials
    ctx_zero_kernel<<<(8 * 64 * 272 + 255) / 256, 256>>>();

    // 3) fused QKV GEMM + inline context reduction -> g_q, g_ctx_part
    qkvctx_kernel<<<Mtot / 128, 256, SMEM_QC>>>(qkv_w);

    // 4) reduce partials + fold ctx into proj weights
    meff_kernel<<<8, 256>>>(proj_w);

    // 5) fused dinv-scale + proj GEMM + bias + transpose + residual -> out
    fused_proj_kernel<<<Mtot / 128, 256, SMEM_K4>>>(x, proj_b, out);
}